// round 3
// baseline (speedup 1.0000x reference)
#include <cuda_runtime.h>
#include <stdint.h>

// BFP quantizer: x (64, 256, 56, 56) fp32 NCHW, tile=8 along C (axis 1).
// bitwidth=16 -> m=7, qmax=127, step=2^(shared_exp-6).
// shared_exp = floor(log2(max(|x| over tile), eps)), eps=2^-23.
//
// R3: each thread handles two CONSECUTIVE float4s (2*w, 2*w+1) so a warp's
// accesses per channel form one contiguous 1KB block (vs two 512B chunks
// 1.5KB apart in R2) -> better DRAM row locality for the mixed r/w stream.
// Streaming hints kept (zero-reuse data).

#define N_DIM   64
#define C_DIM   256
#define HW_DIM  3136               // 56*56
#define TILE_C  8
#define NTILES  (C_DIM / TILE_C)   // 32
#define HW4     (HW_DIM / 4)       // 784
#define HW8     (HW4 / 2)          // 392 pairs of float4 per channel
#define EPS_F   1.1920928955078125e-07f  // 2^-23

__global__ __launch_bounds__(256)
void bfp_quant_kernel(const float4* __restrict__ in, float4* __restrict__ out)
{
    int t = blockIdx.x * blockDim.x + threadIdx.x;
    // t in [0, N*NTILES*HW8)
    int w    = t % HW8;            // pair index
    int rest = t / HW8;
    int ct   = rest % NTILES;
    int n    = rest / NTILES;

    // base in float4 units; this thread covers float4s (2w, 2w+1) per channel
    long base = (long)n * (C_DIM * HW4) + (long)ct * (TILE_C * HW4) + 2 * w;

    // Front-batched: 16 streaming LDG.128, consecutive pairs
    float a[TILE_C][2][4];
    #pragma unroll
    for (int k = 0; k < TILE_C; k++) {
        float4 v0 = __ldcs(&in[base + (long)k * HW4]);
        float4 v1 = __ldcs(&in[base + (long)k * HW4 + 1]);
        a[k][0][0] = v0.x; a[k][0][1] = v0.y; a[k][0][2] = v0.z; a[k][0][3] = v0.w;
        a[k][1][0] = v1.x; a[k][1][1] = v1.y; a[k][1][2] = v1.z; a[k][1][3] = v1.w;
    }

    #pragma unroll
    for (int g = 0; g < 2; g++) {
        #pragma unroll
        for (int j = 0; j < 4; j++) {
            // tile max(|x|) clamped by eps
            float mx = EPS_F;
            #pragma unroll
            for (int k = 0; k < TILE_C; k++)
                mx = fmaxf(mx, fabsf(a[k][g][j]));

            // shared_exp = floor(log2(mx)): exponent bits (mx normal, >0)
            int e = (int)(__float_as_uint(mx) >> 23) - 127;

            // inv_step = 2^(6-e), step = 2^(e-6), both always normal
            float inv_step = __uint_as_float((uint32_t)(133 - e) << 23);
            float step     = __uint_as_float((uint32_t)(e + 121) << 23);

            #pragma unroll
            for (int k = 0; k < TILE_C; k++) {
                float q = rintf(a[k][g][j] * inv_step);   // round-half-even
                q = fminf(fmaxf(q, -127.0f), 127.0f);
                a[k][g][j] = q * step;
            }
        }
    }

    #pragma unroll
    for (int k = 0; k < TILE_C; k++) {
        float4 v0, v1;
        v0.x = a[k][0][0]; v0.y = a[k][0][1]; v0.z = a[k][0][2]; v0.w = a[k][0][3];
        v1.x = a[k][1][0]; v1.y = a[k][1][1]; v1.z = a[k][1][2]; v1.w = a[k][1][3];
        __stcs(&out[base + (long)k * HW4], v0);
        __stcs(&out[base + (long)k * HW4 + 1], v1);
    }
}

extern "C" void kernel_launch(void* const* d_in, const int* in_sizes, int n_in,
                              void* d_out, int out_size)
{
    const float4* in  = (const float4*)d_in[0];
    float4*       out = (float4*)d_out;

    const int total_threads = N_DIM * NTILES * HW8;   // 802,816
    const int block = 256;
    const int grid  = total_threads / block;          // 3136 exactly

    bfp_quant_kernel<<<grid, block>>>(in, out);
}

// round 4
// speedup vs baseline: 1.2733x; 1.2733x over previous
#include <cuda_runtime.h>
#include <stdint.h>

// BFP quantizer: x (64, 256, 56, 56) fp32 NCHW, tile=8 along C (axis 1).
// bitwidth=16 -> m=7, qmax=127, step=2^(shared_exp-6).
// shared_exp = floor(log2(max(|x| over tile), eps)), eps=2^-23.
//
// R4: revert R3's strided pairs (half-dense warp wavefronts doubled L1tex
// work, DRAM 79%->62%). Back to the proven dense shape: thread = (n, c_tile,
// w4), one float4 per channel, 8 front-batched streaming LDG.128, lanes at
// consecutive 16B. Streaming hints kept; block=512 to halve wave count;
// low register footprint restores ~57% occupancy.

#define N_DIM   64
#define C_DIM   256
#define HW_DIM  3136               // 56*56
#define TILE_C  8
#define NTILES  (C_DIM / TILE_C)   // 32
#define HW4     (HW_DIM / 4)       // 784
#define EPS_F   1.1920928955078125e-07f  // 2^-23

__global__ __launch_bounds__(512)
void bfp_quant_kernel(const float4* __restrict__ in, float4* __restrict__ out)
{
    int t = blockIdx.x * blockDim.x + threadIdx.x;
    // t in [0, N*NTILES*HW4)
    int w4   = t % HW4;
    int rest = t / HW4;
    int ct   = rest % NTILES;
    int n    = rest / NTILES;

    long base = (long)n * (C_DIM * HW4) + (long)ct * (TILE_C * HW4) + w4;

    // Front-batched: 8 streaming LDG.128, dense across the warp
    float a[TILE_C][4];
    #pragma unroll
    for (int k = 0; k < TILE_C; k++) {
        float4 v = __ldcs(&in[base + (long)k * HW4]);
        a[k][0] = v.x; a[k][1] = v.y; a[k][2] = v.z; a[k][3] = v.w;
    }

    #pragma unroll
    for (int j = 0; j < 4; j++) {
        // tile max(|x|) clamped by eps
        float mx = EPS_F;
        #pragma unroll
        for (int k = 0; k < TILE_C; k++)
            mx = fmaxf(mx, fabsf(a[k][j]));

        // shared_exp = floor(log2(mx)): exponent bits (mx normal, >0)
        int e = (int)(__float_as_uint(mx) >> 23) - 127;

        // inv_step = 2^(6-e), step = 2^(e-6), both always normal
        float inv_step = __uint_as_float((uint32_t)(133 - e) << 23);
        float step     = __uint_as_float((uint32_t)(e + 121) << 23);

        #pragma unroll
        for (int k = 0; k < TILE_C; k++) {
            float q = rintf(a[k][j] * inv_step);   // round-half-to-even
            q = fminf(fmaxf(q, -127.0f), 127.0f);  // clamp +/-(2^7 - 1)
            a[k][j] = q * step;
        }
    }

    #pragma unroll
    for (int k = 0; k < TILE_C; k++) {
        float4 v;
        v.x = a[k][0]; v.y = a[k][1]; v.z = a[k][2]; v.w = a[k][3];
        __stcs(&out[base + (long)k * HW4], v);
    }
}

extern "C" void kernel_launch(void* const* d_in, const int* in_sizes, int n_in,
                              void* d_out, int out_size)
{
    const float4* in  = (const float4*)d_in[0];
    float4*       out = (float4*)d_out;

    const int total_threads = N_DIM * NTILES * HW4;   // 1,605,632
    const int block = 512;
    const int grid  = total_threads / block;          // 3136 exactly

    bfp_quant_kernel<<<grid, block>>>(in, out);
}